// round 1
// baseline (speedup 1.0000x reference)
#include <cuda_runtime.h>

#define B_   32
#define N_   512
#define IN_  256
#define OUT_ 256
#define EPSF 1e-8f

// Scratch (allocation-free rule: __device__ globals)
__device__ float g_Hs[B_ * N_ * OUT_];   // dis[b,j] * (H W^T + b)
__device__ float g_dis[B_ * N_];         // (deg_hat + eps)^-1/2

// ---------------------------------------------------------------------------
// Kernel 1: deg_hat[b,n] = sum_m A[b,n,m] + 1 ;  dis = rsqrt(deg_hat + eps)
// One warp per row (512 floats = 128 float4, 4 float4/lane).
// ---------------------------------------------------------------------------
__global__ void deg_kernel(const float* __restrict__ A) {
    int row  = blockIdx.x * 8 + (threadIdx.x >> 5);
    int lane = threadIdx.x & 31;
    if (row >= B_ * N_) return;
    const float4* a = reinterpret_cast<const float4*>(A + (size_t)row * N_);
    float s = 0.f;
#pragma unroll
    for (int c = 0; c < 4; c++) {
        float4 v = a[lane + c * 32];
        s += (v.x + v.y) + (v.z + v.w);
    }
#pragma unroll
    for (int o = 16; o > 0; o >>= 1) s += __shfl_xor_sync(0xffffffffu, s, o);
    if (lane == 0) g_dis[row] = rsqrtf(s + 1.0f + EPSF);
}

// ---------------------------------------------------------------------------
// Kernel 2: Hs[m, o] = dis[m] * ( sum_k H[m,k] * W[o,k] + bias[o] )
// M=16384, N=256, K=256. Both operands K-contiguous ("NT").
// 128x128x8 tiles, 256 threads, 8x8 per thread.
// ---------------------------------------------------------------------------
__global__ __launch_bounds__(256)
void gemm1_kernel(const float* __restrict__ H,
                  const float* __restrict__ W,
                  const float* __restrict__ bias) {
    __shared__ float As[8][128];
    __shared__ float Bs[8][128];

    const int bm  = blockIdx.y * 128;
    const int bn  = blockIdx.x * 128;
    const int tid = threadIdx.x;

    // global->shared mapping: 128 rows x 8 k; 2 threads per row (float4 each)
    const int lr = tid >> 1;          // 0..127
    const int lk = (tid & 1) * 4;     // 0 or 4
    // compute mapping: 16x16 threads, 8x8 each
    const int tr = (tid >> 4) * 8;
    const int tc = (tid & 15) * 8;

    float acc[8][8];
#pragma unroll
    for (int i = 0; i < 8; i++)
#pragma unroll
        for (int j = 0; j < 8; j++) acc[i][j] = 0.f;

    for (int k0 = 0; k0 < IN_; k0 += 8) {
        float4 av = *reinterpret_cast<const float4*>(H + (size_t)(bm + lr) * IN_ + k0 + lk);
        float4 bv = *reinterpret_cast<const float4*>(W + (size_t)(bn + lr) * IN_ + k0 + lk);
        As[lk + 0][lr] = av.x; As[lk + 1][lr] = av.y;
        As[lk + 2][lr] = av.z; As[lk + 3][lr] = av.w;
        Bs[lk + 0][lr] = bv.x; Bs[lk + 1][lr] = bv.y;
        Bs[lk + 2][lr] = bv.z; Bs[lk + 3][lr] = bv.w;
        __syncthreads();
#pragma unroll
        for (int k = 0; k < 8; k++) {
            float rm[8], rn[8];
            *reinterpret_cast<float4*>(&rm[0]) = *reinterpret_cast<const float4*>(&As[k][tr]);
            *reinterpret_cast<float4*>(&rm[4]) = *reinterpret_cast<const float4*>(&As[k][tr + 4]);
            *reinterpret_cast<float4*>(&rn[0]) = *reinterpret_cast<const float4*>(&Bs[k][tc]);
            *reinterpret_cast<float4*>(&rn[4]) = *reinterpret_cast<const float4*>(&Bs[k][tc + 4]);
#pragma unroll
            for (int i = 0; i < 8; i++)
#pragma unroll
                for (int j = 0; j < 8; j++) acc[i][j] += rm[i] * rn[j];
        }
        __syncthreads();
    }

    // epilogue: + bias, * dis, store
    float bl[8];
#pragma unroll
    for (int j = 0; j < 8; j++) bl[j] = bias[bn + tc + j];
#pragma unroll
    for (int i = 0; i < 8; i++) {
        int m = bm + tr + i;
        float d = g_dis[m];
        float4 o0, o1;
        o0.x = d * (acc[i][0] + bl[0]); o0.y = d * (acc[i][1] + bl[1]);
        o0.z = d * (acc[i][2] + bl[2]); o0.w = d * (acc[i][3] + bl[3]);
        o1.x = d * (acc[i][4] + bl[4]); o1.y = d * (acc[i][5] + bl[5]);
        o1.z = d * (acc[i][6] + bl[6]); o1.w = d * (acc[i][7] + bl[7]);
        float* dst = g_Hs + (size_t)m * OUT_ + bn + tc;
        *reinterpret_cast<float4*>(dst)     = o0;
        *reinterpret_cast<float4*>(dst + 4) = o1;
    }
}

// ---------------------------------------------------------------------------
// Kernel 3: per batch b:
//   out[i,o] = relu( mask[i] * dis[i] * ( sum_j A[i,j]*Hs[j,o] + Hs[i,o] ) )
// M=512, N=256, K=512 ("NN"). 128x128x8 tiles, grid (2, 4, 32).
// ---------------------------------------------------------------------------
__global__ __launch_bounds__(256)
void gemm2_kernel(const float* __restrict__ A,
                  const float* __restrict__ mask,
                  float* __restrict__ out) {
    __shared__ float As[8][128];
    __shared__ float Bs[8][128];

    const int b   = blockIdx.z;
    const int bm  = blockIdx.y * 128;
    const int bn  = blockIdx.x * 128;
    const int tid = threadIdx.x;

    const float* Ab  = A + (size_t)b * N_ * N_;
    const float* Hsb = g_Hs + (size_t)b * N_ * OUT_;

    // A tile: 128 rows x 8 k (K-contiguous) — 2 threads/row, float4
    const int lr = tid >> 1;
    const int lk = (tid & 1) * 4;
    // Hs tile: 8 k-rows x 128 n (N-contiguous) — direct float4
    const int bk = tid >> 5;          // 0..7
    const int bn4 = (tid & 31) * 4;   // 0..124

    const int tr = (tid >> 4) * 8;
    const int tc = (tid & 15) * 8;

    float acc[8][8];
#pragma unroll
    for (int i = 0; i < 8; i++)
#pragma unroll
        for (int j = 0; j < 8; j++) acc[i][j] = 0.f;

    for (int k0 = 0; k0 < N_; k0 += 8) {
        float4 av = *reinterpret_cast<const float4*>(Ab + (size_t)(bm + lr) * N_ + k0 + lk);
        As[lk + 0][lr] = av.x; As[lk + 1][lr] = av.y;
        As[lk + 2][lr] = av.z; As[lk + 3][lr] = av.w;
        *reinterpret_cast<float4*>(&Bs[bk][bn4]) =
            *reinterpret_cast<const float4*>(Hsb + (size_t)(k0 + bk) * OUT_ + bn + bn4);
        __syncthreads();
#pragma unroll
        for (int k = 0; k < 8; k++) {
            float rm[8], rn[8];
            *reinterpret_cast<float4*>(&rm[0]) = *reinterpret_cast<const float4*>(&As[k][tr]);
            *reinterpret_cast<float4*>(&rm[4]) = *reinterpret_cast<const float4*>(&As[k][tr + 4]);
            *reinterpret_cast<float4*>(&rn[0]) = *reinterpret_cast<const float4*>(&Bs[k][tc]);
            *reinterpret_cast<float4*>(&rn[4]) = *reinterpret_cast<const float4*>(&Bs[k][tc + 4]);
#pragma unroll
            for (int i = 0; i < 8; i++)
#pragma unroll
                for (int j = 0; j < 8; j++) acc[i][j] += rm[i] * rn[j];
        }
        __syncthreads();
    }

    // epilogue: self-loop term + mask * dis, relu
#pragma unroll
    for (int i = 0; i < 8; i++) {
        int m = bm + tr + i;                 // row within batch
        float md = mask[b * N_ + m] * g_dis[b * N_ + m];
        const float* self = Hsb + (size_t)m * OUT_ + bn + tc;
        float4 s0 = *reinterpret_cast<const float4*>(self);
        float4 s1 = *reinterpret_cast<const float4*>(self + 4);
        float4 o0, o1;
        o0.x = fmaxf(0.f, md * (acc[i][0] + s0.x));
        o0.y = fmaxf(0.f, md * (acc[i][1] + s0.y));
        o0.z = fmaxf(0.f, md * (acc[i][2] + s0.z));
        o0.w = fmaxf(0.f, md * (acc[i][3] + s0.w));
        o1.x = fmaxf(0.f, md * (acc[i][4] + s1.x));
        o1.y = fmaxf(0.f, md * (acc[i][5] + s1.y));
        o1.z = fmaxf(0.f, md * (acc[i][6] + s1.z));
        o1.w = fmaxf(0.f, md * (acc[i][7] + s1.w));
        float* dst = out + (size_t)b * N_ * OUT_ + (size_t)m * OUT_ + bn + tc;
        *reinterpret_cast<float4*>(dst)     = o0;
        *reinterpret_cast<float4*>(dst + 4) = o1;
    }
}

// ---------------------------------------------------------------------------
extern "C" void kernel_launch(void* const* d_in, const int* in_sizes, int n_in,
                              void* d_out, int out_size) {
    const float* H    = (const float*)d_in[0];  // (32,512,256)
    const float* A    = (const float*)d_in[1];  // (32,512,512)
    const float* mask = (const float*)d_in[2];  // (32,512)
    const float* W    = (const float*)d_in[3];  // (256,256)
    const float* bias = (const float*)d_in[4];  // (256,)
    float* out = (float*)d_out;                 // (32,512,256)

    // 1) dis = rsqrt(rowsum(A) + 1 + eps)
    deg_kernel<<<(B_ * N_) / 8, 256>>>(A);

    // 2) Hs = dis * (H @ W^T + b)
    {
        dim3 grid(OUT_ / 128, (B_ * N_) / 128);   // (2, 128)
        gemm1_kernel<<<grid, 256>>>(H, W, bias);
    }

    // 3) out = relu(mask * dis * (A @ Hs + Hs))
    {
        dim3 grid(OUT_ / 128, N_ / 128, B_);      // (2, 4, 32)
        gemm2_kernel<<<grid, 256>>>(A, mask, out);
    }
}

// round 4
// speedup vs baseline: 2.1916x; 2.1916x over previous
#include <cuda_runtime.h>
#include <cuda_bf16.h>
#include <cstdint>

#define B_   32
#define N_   512
#define K1_  256
#define O_   256
#define EPSF 1e-8f

// ---- GEMM tiling ----------------------------------------------------------
#define KC      16                       // k per chunk (one m16n8k16 step)
#define A_ROW   48                       // A smem row bytes: 16 bf16 + 12B pad
#define A_PLANE (128 * A_ROW)            // 6144
#define B_ROW   528                      // B smem row bytes: 256 bf16 + 16B pad
#define B_PLANE (KC * B_ROW)             // 8448
#define AUX_SZ  2048
#define STAGE   (2 * A_PLANE + 2 * B_PLANE)   // 29184
#define OFF_AH  0
#define OFF_AL  A_PLANE
#define OFF_BH  (2 * A_PLANE)
#define OFF_BL  (2 * A_PLANE + B_PLANE)
#define SMEM_TOTAL (AUX_SZ + 2 * STAGE)       // 60416

// B pointer advance per K-chunk, in uint4 units: KC rows * O_ u32 / 4
#define BP_STEP ((KC * O_) / 4)               // 1024

// ---- scratch (allocation-free rule: __device__ globals) --------------------
__device__ __align__(16) float    g_dis[B_ * N_];          // rsqrt(deg+1+eps)
__device__ __align__(16) uint32_t g_HsP[B_ * N_ * O_];     // dis_j*(HW^T+b), packed bf16 hi|lo<<16, [b][j][o]
__device__ __align__(16) uint32_t g_WtP[K1_ * O_];         // W^T packed bf16 hi|lo, [k][o]

// ---- helpers ---------------------------------------------------------------
__device__ __forceinline__ void ldsm_x4(uint32_t& r0, uint32_t& r1, uint32_t& r2,
                                        uint32_t& r3, uint32_t addr) {
    asm volatile("ldmatrix.sync.aligned.m8n8.x4.shared.b16 {%0,%1,%2,%3}, [%4];"
                 : "=r"(r0), "=r"(r1), "=r"(r2), "=r"(r3) : "r"(addr));
}
__device__ __forceinline__ void ldsm_x2t(uint32_t& r0, uint32_t& r1, uint32_t addr) {
    asm volatile("ldmatrix.sync.aligned.m8n8.x2.trans.shared.b16 {%0,%1}, [%2];"
                 : "=r"(r0), "=r"(r1) : "r"(addr));
}
__device__ __forceinline__ void mma16816(float* c,
                                         uint32_t a0, uint32_t a1, uint32_t a2, uint32_t a3,
                                         uint32_t b0, uint32_t b1) {
    asm volatile("mma.sync.aligned.m16n8k16.row.col.f32.bf16.bf16.f32 "
                 "{%0,%1,%2,%3}, {%4,%5,%6,%7}, {%8,%9}, {%0,%1,%2,%3};"
                 : "+f"(c[0]), "+f"(c[1]), "+f"(c[2]), "+f"(c[3])
                 : "r"(a0), "r"(a1), "r"(a2), "r"(a3), "r"(b0), "r"(b1));
}
// fp32 -> (bf16 hi, bf16 lo) residual split, 4 at a time
__device__ __forceinline__ void split4(float4 f, uint2& hi, uint2& lo) {
    __nv_bfloat162 h01 = __floats2bfloat162_rn(f.x, f.y);
    __nv_bfloat162 h23 = __floats2bfloat162_rn(f.z, f.w);
    uint32_t u01 = *reinterpret_cast<uint32_t*>(&h01);
    uint32_t u23 = *reinterpret_cast<uint32_t*>(&h23);
    float r0 = f.x - __uint_as_float(u01 << 16);
    float r1 = f.y - __uint_as_float(u01 & 0xFFFF0000u);
    float r2 = f.z - __uint_as_float(u23 << 16);
    float r3 = f.w - __uint_as_float(u23 & 0xFFFF0000u);
    __nv_bfloat162 l01 = __floats2bfloat162_rn(r0, r1);
    __nv_bfloat162 l23 = __floats2bfloat162_rn(r2, r3);
    hi = make_uint2(u01, u23);
    lo = make_uint2(*reinterpret_cast<uint32_t*>(&l01), *reinterpret_cast<uint32_t*>(&l23));
}
__device__ __forceinline__ uint32_t packsplit(float v) {
    uint32_t hu = (uint32_t)__bfloat16_as_ushort(__float2bfloat16_rn(v));
    float r = v - __uint_as_float(hu << 16);
    uint32_t lu = (uint32_t)__bfloat16_as_ushort(__float2bfloat16_rn(r));
    return hu | (lu << 16);
}
__device__ __forceinline__ float unpacksplit(uint32_t q) {
    return __uint_as_float(q << 16) + __uint_as_float(q & 0xFFFF0000u);
}

// smem conversion-stores
__device__ __forceinline__ void stconv_a(char* smem, uint32_t bufo, uint32_t soff, float4 av) {
    uint2 hi, lo; split4(av, hi, lo);
    *reinterpret_cast<uint2*>(smem + bufo + OFF_AH + soff) = hi;
    *reinterpret_cast<uint2*>(smem + bufo + OFF_AL + soff) = lo;
}
__device__ __forceinline__ void stconv_b(char* smem, uint32_t bufo, uint32_t soff,
                                         uint4 q0, uint4 q1) {
    uint4 hv, lv;
    hv.x = __byte_perm(q0.x, q0.y, 0x5410); hv.y = __byte_perm(q0.z, q0.w, 0x5410);
    hv.z = __byte_perm(q1.x, q1.y, 0x5410); hv.w = __byte_perm(q1.z, q1.w, 0x5410);
    lv.x = __byte_perm(q0.x, q0.y, 0x7632); lv.y = __byte_perm(q0.z, q0.w, 0x7632);
    lv.z = __byte_perm(q1.x, q1.y, 0x7632); lv.w = __byte_perm(q1.z, q1.w, 0x7632);
    *reinterpret_cast<uint4*>(smem + bufo + OFF_BH + soff) = hv;
    *reinterpret_cast<uint4*>(smem + bufo + OFF_BL + soff) = lv;
}

// per-chunk mma: 3 split terms, warp tile 64x32
__device__ __forceinline__ void chunk_mma(float acc[4][4][4], uint32_t bufb,
                                          int wm, int wn, int lane) {
    const uint32_t arow = (uint32_t)((lane & 7) + ((lane >> 3) & 1) * 8);
    const uint32_t a_base = bufb + OFF_AH + (wm * 64 + arow) * A_ROW + (lane >> 4) * 16;
    const uint32_t b_base = bufb + OFF_BH + (lane & 15) * B_ROW + (wn * 32) * 2;

    uint32_t a[4][4], bh[4][2], bl[4][2];
#pragma unroll
    for (int mi = 0; mi < 4; mi++)
        ldsm_x4(a[mi][0], a[mi][1], a[mi][2], a[mi][3], a_base + mi * 16 * A_ROW);
#pragma unroll
    for (int n = 0; n < 4; n++) {
        ldsm_x2t(bh[n][0], bh[n][1], b_base + n * 16);
        ldsm_x2t(bl[n][0], bl[n][1], b_base + (OFF_BL - OFF_BH) + n * 16);
    }
#pragma unroll
    for (int mi = 0; mi < 4; mi++)
#pragma unroll
        for (int n = 0; n < 4; n++) {
            mma16816(acc[mi][n], a[mi][0], a[mi][1], a[mi][2], a[mi][3], bh[n][0], bh[n][1]);
            mma16816(acc[mi][n], a[mi][0], a[mi][1], a[mi][2], a[mi][3], bl[n][0], bl[n][1]);
        }
#pragma unroll
    for (int mi = 0; mi < 4; mi++)   // A-lo pass (reuse regs)
        ldsm_x4(a[mi][0], a[mi][1], a[mi][2], a[mi][3],
                a_base + (OFF_AL - OFF_AH) + mi * 16 * A_ROW);
#pragma unroll
    for (int mi = 0; mi < 4; mi++)
#pragma unroll
        for (int n = 0; n < 4; n++)
            mma16816(acc[mi][n], a[mi][0], a[mi][1], a[mi][2], a[mi][3], bh[n][0], bh[n][1]);
}

// ---------------------------------------------------------------------------
// deg: dis = rsqrt(rowsum(A)+1+eps). 4 rows/warp for MLP=16.
// ---------------------------------------------------------------------------
__global__ void deg_kernel(const float* __restrict__ A) {
    int wid = threadIdx.x >> 5, lane = threadIdx.x & 31;
    int row0 = (blockIdx.x * 8 + wid) * 4;
    const float4* a = reinterpret_cast<const float4*>(A + (size_t)row0 * N_);
    float s[4] = {0.f, 0.f, 0.f, 0.f};
#pragma unroll
    for (int c = 0; c < 4; c++)
#pragma unroll
        for (int r = 0; r < 4; r++) {
            float4 v = a[(size_t)r * 128 + lane + c * 32];
            s[r] += (v.x + v.y) + (v.z + v.w);
        }
#pragma unroll
    for (int o = 16; o > 0; o >>= 1)
#pragma unroll
        for (int r = 0; r < 4; r++) s[r] += __shfl_xor_sync(0xffffffffu, s[r], o);
    if (lane == 0)
#pragma unroll
        for (int r = 0; r < 4; r++) g_dis[row0 + r] = rsqrtf(s[r] + 1.0f + EPSF);
}

// ---------------------------------------------------------------------------
// Wt: g_WtP[k][o] = packsplit(W[o][k])   (32x32 smem transpose tiles)
// ---------------------------------------------------------------------------
__global__ void wt_kernel(const float* __restrict__ W) {
    __shared__ float tile[32][33];
    int k0 = blockIdx.x * 32, o0 = blockIdx.y * 32;
    int tx = threadIdx.x, ty = threadIdx.y;   // (32, 8)
#pragma unroll
    for (int i = 0; i < 32; i += 8)
        tile[ty + i][tx] = W[(size_t)(o0 + ty + i) * K1_ + k0 + tx];   // tile[o][k]
    __syncthreads();
#pragma unroll
    for (int i = 0; i < 32; i += 8)
        g_WtP[(size_t)(k0 + ty + i) * O_ + o0 + tx] = packsplit(tile[tx][ty + i]);
}

// ---------------------------------------------------------------------------
// GEMM1: Hs[m,o] = dis[m] * (sum_k H[m,k] W[o,k] + b[o]), store packed.
// CTA 128(M) x 256(N=o), K=256 in 16 chunks. 512 thr, 128 CTAs (1 wave).
// ---------------------------------------------------------------------------
__global__ __launch_bounds__(512, 1)
void gemm1_mma(const float* __restrict__ H, const float* __restrict__ bias) {
    extern __shared__ char smem[];
    const uint32_t sb = (uint32_t)__cvta_generic_to_shared(smem);
    const int t = threadIdx.x, lane = t & 31, wid = t >> 5;
    const int wm = wid >> 3, wn = wid & 7;
    const int bm = blockIdx.x * 128;

    float* bias_s = reinterpret_cast<float*>(smem);          // 256 f
    float* dis_s  = reinterpret_cast<float*>(smem + 1024);   // 128 f
    if (t < 256) bias_s[t] = bias[t];
    if (t < 128) dis_s[t]  = g_dis[bm + t];

    const float4* ap = reinterpret_cast<const float4*>(
        H + (size_t)(bm + (t >> 2)) * K1_) + (t & 3);
    const uint4* bp = reinterpret_cast<const uint4*>(
        g_WtP + (size_t)(t >> 5) * O_ + (t & 31) * 8);
    const uint32_t a_soff = (uint32_t)((t >> 2) * A_ROW + (t & 3) * 8);
    const uint32_t b_soff = (uint32_t)((t >> 5) * B_ROW + (t & 31) * 16);

    float acc[4][4][4];
#pragma unroll
    for (int i = 0; i < 4; i++)
#pragma unroll
        for (int j = 0; j < 4; j++)
#pragma unroll
            for (int e = 0; e < 4; e++) acc[i][j][e] = 0.f;

    // prologue: chunk 0
    {
        float4 av = ap[0]; uint4 q0 = bp[0], q1 = bp[1];
        ap += 4; bp += BP_STEP;
        stconv_a(smem, AUX_SZ, a_soff, av);
        stconv_b(smem, AUX_SZ, b_soff, q0, q1);
    }
    __syncthreads();

    const int S = K1_ / KC;  // 16
    for (int s = 0; s < S; s++) {
        float4 av; uint4 q0, q1;
        const bool pf = (s + 1 < S);
        if (pf) { av = ap[0]; q0 = bp[0]; q1 = bp[1]; ap += 4; bp += BP_STEP; }
        chunk_mma(acc, sb + AUX_SZ + (uint32_t)(s & 1) * STAGE, wm, wn, lane);
        if (pf) {
            uint32_t bo = AUX_SZ + (uint32_t)((s + 1) & 1) * STAGE;
            stconv_a(smem, bo, a_soff, av);
            stconv_b(smem, bo, b_soff, q0, q1);
        }
        __syncthreads();
    }

    // epilogue: +bias, *dis, split-pack store
    const int g = lane >> 2, i4 = lane & 3;
#pragma unroll
    for (int mi = 0; mi < 4; mi++) {
        int r0 = wm * 64 + mi * 16 + g;
        float d0 = dis_s[r0], d1 = dis_s[r0 + 8];
        uint32_t* dst0 = g_HsP + (size_t)(bm + r0) * O_;
        uint32_t* dst1 = dst0 + 8 * O_;
#pragma unroll
        for (int n = 0; n < 4; n++) {
            int o = wn * 32 + n * 8 + i4 * 2;
            float b0 = bias_s[o], b1 = bias_s[o + 1];
            dst0[o]     = packsplit((acc[mi][n][0] + b0) * d0);
            dst0[o + 1] = packsplit((acc[mi][n][1] + b1) * d0);
            dst1[o]     = packsplit((acc[mi][n][2] + b0) * d1);
            dst1[o + 1] = packsplit((acc[mi][n][3] + b1) * d1);
        }
    }
}

// ---------------------------------------------------------------------------
// GEMM2: out[b,i,o] = relu(mask*dis_i * (sum_j A[i,j] Hs[j,o] + Hs[i,o]))
// CTA 128(M=i) x 256(N=o), K=512 in 32 chunks. grid (4, 32) = 128 CTAs.
// ---------------------------------------------------------------------------
__global__ __launch_bounds__(512, 1)
void gemm2_mma(const float* __restrict__ A, const float* __restrict__ mask,
               float* __restrict__ out) {
    extern __shared__ char smem[];
    const uint32_t sb = (uint32_t)__cvta_generic_to_shared(smem);
    const int t = threadIdx.x, lane = t & 31, wid = t >> 5;
    const int wm = wid >> 3, wn = wid & 7;
    const int i0 = blockIdx.x * 128;
    const int b  = blockIdx.y;

    float* mdis_s = reinterpret_cast<float*>(smem);           // 128 f
    if (t < 128) mdis_s[t] = mask[b * N_ + i0 + t] * g_dis[b * N_ + i0 + t];

    const float4* ap = reinterpret_cast<const float4*>(
        A + ((size_t)b * N_ + i0 + (t >> 2)) * N_) + (t & 3);
    const uint4* bp = reinterpret_cast<const uint4*>(
        g_HsP + (size_t)b * N_ * O_ + (size_t)(t >> 5) * O_ + (t & 31) * 8);
    const uint32_t a_soff = (uint32_t)((t >> 2) * A_ROW + (t & 3) * 8);
    const uint32_t b_soff = (uint32_t)((t >> 5) * B_ROW + (t & 31) * 16);

    float acc[4][4][4];
#pragma unroll
    for (int i = 0; i < 4; i++)
#pragma unroll
        for (int j = 0; j < 4; j++)
#pragma unroll
            for (int e = 0; e < 4; e++) acc[i][j][e] = 0.f;

    {
        float4 av = ap[0]; uint4 q0 = bp[0], q1 = bp[1];
        ap += 4; bp += BP_STEP;
        stconv_a(smem, AUX_SZ, a_soff, av);
        stconv_b(smem, AUX_SZ, b_soff, q0, q1);
    }
    __syncthreads();

    const int S = N_ / KC;  // 32
    for (int s = 0; s < S; s++) {
        float4 av; uint4 q0, q1;
        const bool pf = (s + 1 < S);
        if (pf) { av = ap[0]; q0 = bp[0]; q1 = bp[1]; ap += 4; bp += BP_STEP; }
        chunk_mma(acc, sb + AUX_SZ + (uint32_t)(s & 1) * STAGE, wm, wn, lane);
        if (pf) {
            uint32_t bo = AUX_SZ + (uint32_t)((s + 1) & 1) * STAGE;
            stconv_a(smem, bo, a_soff, av);
            stconv_b(smem, bo, b_soff, q0, q1);
        }
        __syncthreads();
    }

    // epilogue: + self-loop Hs[i,o], * mask*dis_i, relu
    const int g = lane >> 2, i4 = lane & 3;
#pragma unroll
    for (int mi = 0; mi < 4; mi++) {
        int r0 = wm * 64 + mi * 16 + g;
        float md0 = mdis_s[r0], md1 = mdis_s[r0 + 8];
        size_t row0 = ((size_t)b * N_ + i0 + r0) * O_;
        size_t row1 = row0 + 8 * O_;
#pragma unroll
        for (int n = 0; n < 4; n++) {
            int o = wn * 32 + n * 8 + i4 * 2;
            float s00 = unpacksplit(g_HsP[row0 + o]);
            float s01 = unpacksplit(g_HsP[row0 + o + 1]);
            float s10 = unpacksplit(g_HsP[row1 + o]);
            float s11 = unpacksplit(g_HsP[row1 + o + 1]);
            out[row0 + o]     = fmaxf(0.f, md0 * (acc[mi][n][0] + s00));
            out[row0 + o + 1] = fmaxf(0.f, md0 * (acc[mi][n][1] + s01));
            out[row1 + o]     = fmaxf(0.f, md1 * (acc[mi][n][2] + s10));
            out[row1 + o + 1] = fmaxf(0.f, md1 * (acc[mi][n][3] + s11));
        }
    }
}

// ---------------------------------------------------------------------------
extern "C" void kernel_launch(void* const* d_in, const int* in_sizes, int n_in,
                              void* d_out, int out_size) {
    const float* H    = (const float*)d_in[0];  // (32,512,256)
    const float* A    = (const float*)d_in[1];  // (32,512,512)
    const float* mask = (const float*)d_in[2];  // (32,512)
    const float* W    = (const float*)d_in[3];  // (256,256)
    const float* bias = (const float*)d_in[4];  // (256,)
    float* out = (float*)d_out;                 // (32,512,256)

    cudaFuncSetAttribute(gemm1_mma, cudaFuncAttributeMaxDynamicSharedMemorySize, SMEM_TOTAL);
    cudaFuncSetAttribute(gemm2_mma, cudaFuncAttributeMaxDynamicSharedMemorySize, SMEM_TOTAL);

    deg_kernel<<<(B_ * N_) / 32, 256>>>(A);           // 512 blocks
    wt_kernel<<<dim3(8, 8), dim3(32, 8)>>>(W);
    gemm1_mma<<<(B_ * N_) / 128, 512, SMEM_TOTAL>>>(H, bias);
    gemm2_mma<<<dim3(4, B_), 512, SMEM_TOTAL>>>(A, mask, out);
}

// round 6
// speedup vs baseline: 2.2994x; 1.0492x over previous
#include <cuda_runtime.h>
#include <cuda_bf16.h>
#include <cstdint>

#define B_   32
#define N_   512
#define K1_  256
#define O_   256
#define EPSF 1e-8f

// ---- GEMM tiling: CTA 128m x 128n, KC=16, 256 threads (8 warps, 2x4) ------
#define KC      16
#define A_ROW   48                        // 16 bf16 + 12B pad (stride 48 = 3*16)
#define A_PLANE (128 * A_ROW)             // 6144
#define B_ROW   272                       // 128 bf16 + 16B pad (stride 17*16)
#define B_PLANE (KC * B_ROW)              // 4352
#define AUX_SZ  2048
#define STAGE   (2 * A_PLANE + 2 * B_PLANE)   // 20992
#define OFF_AH  0
#define OFF_AL  A_PLANE
#define OFF_BH  (2 * A_PLANE)
#define OFF_BL  (2 * A_PLANE + B_PLANE)
#define SMEM_TOTAL (AUX_SZ + 2 * STAGE)       // 44032 -> 2 CTAs/SM

#define BP_STEP ((KC * O_) / 4)               // uint4 units per K-chunk

// ---- scratch ----------------------------------------------------------------
__device__ __align__(16) float    g_dis[B_ * N_];
__device__ __align__(16) uint32_t g_HsP[B_ * N_ * O_];   // dis_j*(HW^T+b), packed bf16 hi|lo
__device__ __align__(16) uint32_t g_WtP[K1_ * O_];       // W^T packed bf16 hi|lo, [k][o]

// ---- helpers ------------------------------------------------------------------
__device__ __forceinline__ void ldsm_x4(uint32_t& r0, uint32_t& r1, uint32_t& r2,
                                        uint32_t& r3, uint32_t addr) {
    asm volatile("ldmatrix.sync.aligned.m8n8.x4.shared.b16 {%0,%1,%2,%3}, [%4];"
                 : "=r"(r0), "=r"(r1), "=r"(r2), "=r"(r3) : "r"(addr));
}
__device__ __forceinline__ void ldsm_x2t(uint32_t& r0, uint32_t& r1, uint32_t addr) {
    asm volatile("ldmatrix.sync.aligned.m8n8.x2.trans.shared.b16 {%0,%1}, [%2];"
                 : "=r"(r0), "=r"(r1) : "r"(addr));
}
__device__ __forceinline__ void mma16816(float* c,
                                         uint32_t a0, uint32_t a1, uint32_t a2, uint32_t a3,
                                         uint32_t b0, uint32_t b1) {
    asm volatile("mma.sync.aligned.m16n8k16.row.col.f32.bf16.bf16.f32 "
                 "{%0,%1,%2,%3}, {%4,%5,%6,%7}, {%8,%9}, {%0,%1,%2,%3};"
                 : "+f"(c[0]), "+f"(c[1]), "+f"(c[2]), "+f"(c[3])
                 : "r"(a0), "r"(a1), "r"(a2), "r"(a3), "r"(b0), "r"(b1));
}
__device__ __forceinline__ void split4(float4 f, uint2& hi, uint2& lo) {
    __nv_bfloat162 h01 = __floats2bfloat162_rn(f.x, f.y);
    __nv_bfloat162 h23 = __floats2bfloat162_rn(f.z, f.w);
    uint32_t u01 = *reinterpret_cast<uint32_t*>(&h01);
    uint32_t u23 = *reinterpret_cast<uint32_t*>(&h23);
    float r0 = f.x - __uint_as_float(u01 << 16);
    float r1 = f.y - __uint_as_float(u01 & 0xFFFF0000u);
    float r2 = f.z - __uint_as_float(u23 << 16);
    float r3 = f.w - __uint_as_float(u23 & 0xFFFF0000u);
    __nv_bfloat162 l01 = __floats2bfloat162_rn(r0, r1);
    __nv_bfloat162 l23 = __floats2bfloat162_rn(r2, r3);
    hi = make_uint2(u01, u23);
    lo = make_uint2(*reinterpret_cast<uint32_t*>(&l01), *reinterpret_cast<uint32_t*>(&l23));
}
__device__ __forceinline__ uint32_t packsplit(float v) {
    uint32_t hu = (uint32_t)__bfloat16_as_ushort(__float2bfloat16_rn(v));
    float r = v - __uint_as_float(hu << 16);
    uint32_t lu = (uint32_t)__bfloat16_as_ushort(__float2bfloat16_rn(r));
    return hu | (lu << 16);
}
__device__ __forceinline__ float unpacksplit(uint32_t q) {
    return __uint_as_float(q << 16) + __uint_as_float(q & 0xFFFF0000u);
}

// store A chunk slice (two consecutive float4 = 8 k) split into hi/lo planes
__device__ __forceinline__ void stconv_a(char* smem, uint32_t bufo, uint32_t soff,
                                         float4 a0, float4 a1) {
    uint2 h0, l0, h1, l1;
    split4(a0, h0, l0); split4(a1, h1, l1);
    *reinterpret_cast<uint4*>(smem + bufo + OFF_AH + soff) = make_uint4(h0.x, h0.y, h1.x, h1.y);
    *reinterpret_cast<uint4*>(smem + bufo + OFF_AL + soff) = make_uint4(l0.x, l0.y, l1.x, l1.y);
}
__device__ __forceinline__ void stconv_b(char* smem, uint32_t bufo, uint32_t soff,
                                         uint4 q0, uint4 q1) {
    uint4 hv, lv;
    hv.x = __byte_perm(q0.x, q0.y, 0x5410); hv.y = __byte_perm(q0.z, q0.w, 0x5410);
    hv.z = __byte_perm(q1.x, q1.y, 0x5410); hv.w = __byte_perm(q1.z, q1.w, 0x5410);
    lv.x = __byte_perm(q0.x, q0.y, 0x7632); lv.y = __byte_perm(q0.z, q0.w, 0x7632);
    lv.z = __byte_perm(q1.x, q1.y, 0x7632); lv.w = __byte_perm(q1.z, q1.w, 0x7632);
    *reinterpret_cast<uint4*>(smem + bufo + OFF_BH + soff) = hv;
    *reinterpret_cast<uint4*>(smem + bufo + OFF_BL + soff) = lv;
}

// per-chunk mma: 3 split terms, warp tile 64x32, wm in {0,1}, wn in {0..3}
__device__ __forceinline__ void chunk_mma(float acc[4][4][4], uint32_t bufb,
                                          int wm, int wn, int lane) {
    const uint32_t arow = (uint32_t)((lane & 7) + ((lane >> 3) & 1) * 8);
    const uint32_t a_base = bufb + OFF_AH + (wm * 64 + arow) * A_ROW + (lane >> 4) * 16;
    const uint32_t b_base = bufb + OFF_BH + (lane & 15) * B_ROW + (wn * 32) * 2;

    uint32_t a[4][4], bh[4][2], bl[4][2];
#pragma unroll
    for (int mi = 0; mi < 4; mi++)
        ldsm_x4(a[mi][0], a[mi][1], a[mi][2], a[mi][3], a_base + mi * 16 * A_ROW);
#pragma unroll
    for (int n = 0; n < 4; n++) {
        ldsm_x2t(bh[n][0], bh[n][1], b_base + n * 16);
        ldsm_x2t(bl[n][0], bl[n][1], b_base + (OFF_BL - OFF_BH) + n * 16);
    }
#pragma unroll
    for (int mi = 0; mi < 4; mi++)
#pragma unroll
        for (int n = 0; n < 4; n++) {
            mma16816(acc[mi][n], a[mi][0], a[mi][1], a[mi][2], a[mi][3], bh[n][0], bh[n][1]);
            mma16816(acc[mi][n], a[mi][0], a[mi][1], a[mi][2], a[mi][3], bl[n][0], bl[n][1]);
        }
#pragma unroll
    for (int mi = 0; mi < 4; mi++)
        ldsm_x4(a[mi][0], a[mi][1], a[mi][2], a[mi][3],
                a_base + (OFF_AL - OFF_AH) + mi * 16 * A_ROW);
#pragma unroll
    for (int mi = 0; mi < 4; mi++)
#pragma unroll
        for (int n = 0; n < 4; n++)
            mma16816(acc[mi][n], a[mi][0], a[mi][1], a[mi][2], a[mi][3], bh[n][0], bh[n][1]);
}

// ---------------------------------------------------------------------------
// prep: blocks [0,512): deg (32 rows each = all 16384); blocks [512,576): Wt.
// ---------------------------------------------------------------------------
#define DEG_BLKS 512
__global__ __launch_bounds__(256)
void prep_kernel(const float* __restrict__ A, const float* __restrict__ W) {
    __shared__ float tile[32][33];
    const int t = threadIdx.x;
    if (blockIdx.x < DEG_BLKS) {
        int wid = t >> 5, lane = t & 31;
        int row0 = (blockIdx.x * 8 + wid) * 4;
        const float4* a = reinterpret_cast<const float4*>(A + (size_t)row0 * N_);
        float s[4] = {0.f, 0.f, 0.f, 0.f};
#pragma unroll
        for (int c = 0; c < 4; c++)
#pragma unroll
            for (int r = 0; r < 4; r++) {
                float4 v = a[(size_t)r * 128 + lane + c * 32];
                s[r] += (v.x + v.y) + (v.z + v.w);
            }
#pragma unroll
        for (int o = 16; o > 0; o >>= 1)
#pragma unroll
            for (int r = 0; r < 4; r++) s[r] += __shfl_xor_sync(0xffffffffu, s[r], o);
        if (lane == 0)
#pragma unroll
            for (int r = 0; r < 4; r++) g_dis[row0 + r] = rsqrtf(s[r] + 1.0f + EPSF);
    } else {
        int idx = blockIdx.x - DEG_BLKS;       // 64 tiles: 8x8
        int k0 = (idx & 7) * 32, o0 = (idx >> 3) * 32;
        int tx = t & 31, ty = t >> 5;          // (32, 8)
#pragma unroll
        for (int i = 0; i < 32; i += 8)
            tile[ty + i][tx] = W[(size_t)(o0 + ty + i) * K1_ + k0 + tx];
        __syncthreads();
#pragma unroll
        for (int i = 0; i < 32; i += 8)
            g_WtP[(size_t)(k0 + ty + i) * O_ + o0 + tx] = packsplit(tile[tx][ty + i]);
    }
}

// ---------------------------------------------------------------------------
// GEMM1: Hs[m,o] = dis[m]*(sum_k H[m,k] W[o,k] + b[o]). CTA 128x128.
// grid (128 m-tiles, 2 o-tiles) = 256 CTAs, 2/SM.
// ---------------------------------------------------------------------------
__global__ __launch_bounds__(256, 2)
void gemm1_mma(const float* __restrict__ H, const float* __restrict__ bias) {
    extern __shared__ char smem[];
    const uint32_t sb = (uint32_t)__cvta_generic_to_shared(smem);
    const int t = threadIdx.x, lane = t & 31, wid = t >> 5;
    const int wm = wid >> 2, wn = wid & 3;
    const int bm = blockIdx.x * 128;
    const int bn = blockIdx.y * 128;

    float* bias_s = reinterpret_cast<float*>(smem);          // 128 f (this n-tile)
    float* dis_s  = reinterpret_cast<float*>(smem + 1024);   // 128 f
    if (t < 128) { bias_s[t] = bias[bn + t]; dis_s[t] = g_dis[bm + t]; }

    const int ar = t >> 1, ac = (t & 1) * 2;
    const float4* ap = reinterpret_cast<const float4*>(
        H + (size_t)(bm + ar) * K1_) + ac;
    const uint4* bp = reinterpret_cast<const uint4*>(
        g_WtP + (size_t)(t >> 4) * O_ + bn + (t & 15) * 8);
    const uint32_t a_soff = (uint32_t)(ar * A_ROW + ac * 8);
    const uint32_t b_soff = (uint32_t)((t >> 4) * B_ROW + (t & 15) * 16);

    float acc[4][4][4];
#pragma unroll
    for (int i = 0; i < 4; i++)
#pragma unroll
        for (int j = 0; j < 4; j++)
#pragma unroll
            for (int e = 0; e < 4; e++) acc[i][j][e] = 0.f;

    {
        float4 a0 = ap[0], a1 = ap[1]; uint4 q0 = bp[0], q1 = bp[1];
        ap += 4; bp += BP_STEP;
        stconv_a(smem, AUX_SZ, a_soff, a0, a1);
        stconv_b(smem, AUX_SZ, b_soff, q0, q1);
    }
    __syncthreads();

    const int S = K1_ / KC;  // 16
    for (int s = 0; s < S; s++) {
        float4 a0, a1; uint4 q0, q1;
        const bool pf = (s + 1 < S);
        if (pf) { a0 = ap[0]; a1 = ap[1]; q0 = bp[0]; q1 = bp[1]; ap += 4; bp += BP_STEP; }
        chunk_mma(acc, sb + AUX_SZ + (uint32_t)(s & 1) * STAGE, wm, wn, lane);
        if (pf) {
            uint32_t bo = AUX_SZ + (uint32_t)((s + 1) & 1) * STAGE;
            stconv_a(smem, bo, a_soff, a0, a1);
            stconv_b(smem, bo, b_soff, q0, q1);
        }
        __syncthreads();
    }

    const int g = lane >> 2, i4 = lane & 3;
#pragma unroll
    for (int mi = 0; mi < 4; mi++) {
        int r0 = wm * 64 + mi * 16 + g;
        float d0 = dis_s[r0], d1 = dis_s[r0 + 8];
        uint32_t* dst0 = g_HsP + (size_t)(bm + r0) * O_ + bn;
        uint32_t* dst1 = dst0 + 8 * O_;
#pragma unroll
        for (int n = 0; n < 4; n++) {
            int o = wn * 32 + n * 8 + i4 * 2;
            float b0 = bias_s[o], b1 = bias_s[o + 1];
            dst0[o]     = packsplit((acc[mi][n][0] + b0) * d0);
            dst0[o + 1] = packsplit((acc[mi][n][1] + b1) * d0);
            dst1[o]     = packsplit((acc[mi][n][2] + b0) * d1);
            dst1[o + 1] = packsplit((acc[mi][n][3] + b1) * d1);
        }
    }
}

// ---------------------------------------------------------------------------
// GEMM2: out[b,i,o] = relu(mask*dis_i*(sum_j A[i,j] Hs[j,o] + Hs[i,o])).
// CTA 128x128, grid (4 i-tiles, 2 o-tiles, 32 b) = 256 CTAs, 2/SM.
// ---------------------------------------------------------------------------
__global__ __launch_bounds__(256, 2)
void gemm2_mma(const float* __restrict__ A, const float* __restrict__ mask,
               float* __restrict__ out) {
    extern __shared__ char smem[];
    const uint32_t sb = (uint32_t)__cvta_generic_to_shared(smem);
    const int t = threadIdx.x, lane = t & 31, wid = t >> 5;
    const int wm = wid >> 2, wn = wid & 3;
    const int i0 = blockIdx.x * 128;
    const int bn = blockIdx.y * 128;
    const int b  = blockIdx.z;

    float* mdis_s = reinterpret_cast<float*>(smem);   // 128 f
    if (t < 128) mdis_s[t] = mask[b * N_ + i0 + t] * g_dis[b * N_ + i0 + t];

    const int ar = t >> 1, ac = (t & 1) * 2;
    const float4* ap = reinterpret_cast<const float4*>(
        A + ((size_t)b * N_ + i0 + ar) * N_) + ac;
    const uint4* bp = reinterpret_cast<const uint4*>(
        g_HsP + (size_t)b * N_ * O_ + (size_t)(t >> 4) * O_ + bn + (t & 15) * 8);
    const uint32_t a_soff = (uint32_t)(ar * A_ROW + ac * 8);
    const uint32_t b_soff = (uint32_t)((t >> 4) * B_ROW + (t & 15) * 16);

    float acc[4][4][4];
#pragma unroll
    for (int i = 0; i < 4; i++)
#pragma unroll
        for (int j = 0; j < 4; j++)
#pragma unroll
            for (int e = 0; e < 4; e++) acc[i][j][e] = 0.f;

    {
        float4 a0 = ap[0], a1 = ap[1]; uint4 q0 = bp[0], q1 = bp[1];
        ap += 4; bp += BP_STEP;
        stconv_a(smem, AUX_SZ, a_soff, a0, a1);
        stconv_b(smem, AUX_SZ, b_soff, q0, q1);
    }
    __syncthreads();

    const int S = N_ / KC;  // 32
    for (int s = 0; s < S; s++) {
        float4 a0, a1; uint4 q0, q1;
        const bool pf = (s + 1 < S);
        if (pf) { a0 = ap[0]; a1 = ap[1]; q0 = bp[0]; q1 = bp[1]; ap += 4; bp += BP_STEP; }
        chunk_mma(acc, sb + AUX_SZ + (uint32_t)(s & 1) * STAGE, wm, wn, lane);
        if (pf) {
            uint32_t bo = AUX_SZ + (uint32_t)((s + 1) & 1) * STAGE;
            stconv_a(smem, bo, a_soff, a0, a1);
            stconv_b(smem, bo, b_soff, q0, q1);
        }
        __syncthreads();
    }

    const int g = lane >> 2, i4 = lane & 3;
#pragma unroll
    for (int mi = 0; mi < 4; mi++) {
        int r0 = wm * 64 + mi * 16 + g;
        float md0 = mdis_s[r0], md1 = mdis_s[r0 + 8];
        size_t row0 = ((size_t)b * N_ + i0 + r0) * O_ + bn;
        size_t row1 = row0 + 8 * O_;
#pragma unroll
        for (int n = 0; n < 4; n++) {
            int o = wn * 32 + n * 8 + i4 * 2;
            float s00 = unpacksplit(g_HsP[row0 + o]);
            float s01 = unpacksplit(g_HsP[row0 + o + 1]);
            float s10 = unpacksplit(g_HsP[row1 + o]);
            float s11 = unpacksplit(g_HsP[row1 + o + 1]);
            out[row0 + o]     = fmaxf(0.f, md0 * (acc[mi][n][0] + s00));
            out[row0 + o + 1] = fmaxf(0.f, md0 * (acc[mi][n][1] + s01));
            out[row1 + o]     = fmaxf(0.f, md1 * (acc[mi][n][2] + s10));
            out[row1 + o + 1] = fmaxf(0.f, md1 * (acc[mi][n][3] + s11));
        }
    }
}

// ---------------------------------------------------------------------------
extern "C" void kernel_launch(void* const* d_in, const int* in_sizes, int n_in,
                              void* d_out, int out_size) {
    const float* H    = (const float*)d_in[0];
    const float* A    = (const float*)d_in[1];
    const float* mask = (const float*)d_in[2];
    const float* W    = (const float*)d_in[3];
    const float* bias = (const float*)d_in[4];
    float* out = (float*)d_out;

    cudaFuncSetAttribute(gemm1_mma, cudaFuncAttributeMaxDynamicSharedMemorySize, SMEM_TOTAL);
    cudaFuncSetAttribute(gemm2_mma, cudaFuncAttributeMaxDynamicSharedMemorySize, SMEM_TOTAL);

    prep_kernel<<<DEG_BLKS + 64, 256>>>(A, W);
    gemm1_mma<<<dim3(128, 2), 256, SMEM_TOTAL>>>(H, bias);
    gemm2_mma<<<dim3(4, 2, B_), 256, SMEM_TOTAL>>>(A, mask, out);
}